// round 2
// baseline (speedup 1.0000x reference)
#include <cuda_runtime.h>

#define N_MAX   100000
#define HD      128          // NUM_HEADS * HEAD_DIM
#define NHEADS  8

// Scratch (allocation-free rule: __device__ globals)
__device__ float g_Q[N_MAX * HD];
__device__ float g_K[N_MAX * HD];
__device__ float g_V[N_MAX * HD];
__device__ float g_Z[N_MAX * NHEADS];

// ---------------------------------------------------------------------------
// Fused QKV GEMM: out = x @ W + b   (x:[n,128], W:[128,128] row-major)
// blockIdx.y in {0,1,2} selects (Wq,bq,g_Q) / (Wk,bk,g_K) / (Wv,bv,g_V).
// Block tile: 64 rows x 128 cols, full K=128 resident in smem.
// 256 threads, 8x4 register micro-tile per thread.
// ---------------------------------------------------------------------------
__global__ void __launch_bounds__(256)
qkv_gemm(const float* __restrict__ x,
         const float* __restrict__ Wq, const float* __restrict__ bq,
         const float* __restrict__ Wk, const float* __restrict__ bk,
         const float* __restrict__ Wv, const float* __restrict__ bv,
         int n)
{
    const float* W; const float* bias; float* out;
    if (blockIdx.y == 0)      { W = Wq; bias = bq; out = g_Q; }
    else if (blockIdx.y == 1) { W = Wk; bias = bk; out = g_K; }
    else                      { W = Wv; bias = bv; out = g_V; }

    extern __shared__ float smem[];
    float* xs = smem;              // [64][128] row-major
    float* ws = smem + 64 * 128;   // [128][128] row-major (k-major)

    const int tid  = threadIdx.x;
    const int row0 = blockIdx.x * 64;

    // Load x tile: 2048 float4s / 256 threads = 8 each (coalesced, conflict-free)
    #pragma unroll
    for (int j = 0; j < 8; j++) {
        int idx = tid + j * 256;          // float4 index in tile
        int r   = idx >> 5;
        int k4  = idx & 31;
        float4 v = make_float4(0.f, 0.f, 0.f, 0.f);
        int gr = row0 + r;
        if (gr < n) v = *(const float4*)&x[(size_t)gr * 128 + k4 * 4];
        *(float4*)&xs[r * 128 + k4 * 4] = v;
    }
    // Load W: 4096 float4s / 256 threads = 16 each
    #pragma unroll
    for (int j = 0; j < 16; j++) {
        int idx = tid + j * 256;
        *(float4*)&ws[idx * 4] = *(const float4*)&W[idx * 4];
    }
    __syncthreads();

    const int tcol = tid & 31;   // 32 col groups of 4
    const int trow = tid >> 5;   // 8 row groups of 8

    float acc[8][4];
    #pragma unroll
    for (int i = 0; i < 8; i++)
        #pragma unroll
        for (int j = 0; j < 4; j++) acc[i][j] = 0.f;

    #pragma unroll 2
    for (int k = 0; k < 128; k += 4) {
        float4 a[8];
        #pragma unroll
        for (int i = 0; i < 8; i++)
            a[i] = *(float4*)&xs[(trow * 8 + i) * 128 + k];   // warp-broadcast
        #pragma unroll
        for (int kk = 0; kk < 4; kk++) {
            float4 b4 = *(float4*)&ws[(k + kk) * 128 + tcol * 4]; // conflict-free
            #pragma unroll
            for (int i = 0; i < 8; i++) {
                float av = (kk == 0) ? a[i].x : (kk == 1) ? a[i].y
                         : (kk == 2) ? a[i].z : a[i].w;
                acc[i][0] += av * b4.x;
                acc[i][1] += av * b4.y;
                acc[i][2] += av * b4.z;
                acc[i][3] += av * b4.w;
            }
        }
    }

    float4 bb = *(const float4*)&bias[tcol * 4];
    #pragma unroll
    for (int i = 0; i < 8; i++) {
        int gr = row0 + trow * 8 + i;
        if (gr < n) {
            float4 o;
            o.x = acc[i][0] + bb.x;
            o.y = acc[i][1] + bb.y;
            o.z = acc[i][2] + bb.z;
            o.w = acc[i][3] + bb.w;
            *(float4*)&out[(size_t)gr * 128 + tcol * 4] = o;
        }
    }
}

// ---------------------------------------------------------------------------
// Zero d_out (wV accumulator) and g_Z
// ---------------------------------------------------------------------------
__global__ void zero_kernel(float* __restrict__ out, int n_out_f4, int n_z_f4)
{
    int i = blockIdx.x * blockDim.x + threadIdx.x;
    float4 z = make_float4(0.f, 0.f, 0.f, 0.f);
    if (i < n_out_f4) ((float4*)out)[i] = z;
    if (i < n_z_f4)   ((float4*)g_Z)[i] = z;
}

// ---------------------------------------------------------------------------
// Edge phase: one warp per edge.
// edge_index is int32 (JAX x64 disabled: jnp.int64 request silently -> int32).
// lane l owns dims [4l, 4l+3]; head = l>>2 (4 lanes per 16-dim head).
// dot per head via 2x shfl_xor; score = exp(clamp(dot/4, -5, 5));
// scatter score*V[src] into out[dst] via red.global.add.v4.f32,
// score into g_Z[dst*8+head].
// ---------------------------------------------------------------------------
__global__ void __launch_bounds__(256)
edge_kernel(const int* __restrict__ ei, int E, float* __restrict__ out)
{
    int warp = (blockIdx.x * blockDim.x + threadIdx.x) >> 5;
    int lane = threadIdx.x & 31;
    if (warp >= E) return;

    int src = ei[warp];
    int dst = ei[E + warp];

    float4 kv = *(const float4*)&g_K[(size_t)src * 128 + lane * 4];
    float4 qv = *(const float4*)&g_Q[(size_t)dst * 128 + lane * 4];
    float dot = kv.x * qv.x + kv.y * qv.y + kv.z * qv.z + kv.w * qv.w;
    dot += __shfl_xor_sync(0xffffffffu, dot, 1);
    dot += __shfl_xor_sync(0xffffffffu, dot, 2);
    dot *= 0.25f;                                  // 1/sqrt(HEAD_DIM=16)
    dot = fminf(fmaxf(dot, -5.0f), 5.0f);
    float score = __expf(dot);

    float4 vv = *(const float4*)&g_V[(size_t)src * 128 + lane * 4];
    float mx = vv.x * score, my = vv.y * score, mz = vv.z * score, mw = vv.w * score;

    float* p = &out[(size_t)dst * 128 + lane * 4];
    asm volatile("red.global.add.v4.f32 [%0], {%1, %2, %3, %4};"
                 :: "l"(p), "f"(mx), "f"(my), "f"(mz), "f"(mw) : "memory");

    if ((lane & 3) == 0)
        atomicAdd(&g_Z[(size_t)dst * NHEADS + (lane >> 2)], score);
}

// ---------------------------------------------------------------------------
// Normalize in place: out[node, h, d] /= (Z[node, h] + 1e-6)
// ---------------------------------------------------------------------------
__global__ void norm_kernel(float* __restrict__ out, int n)
{
    int i = blockIdx.x * blockDim.x + threadIdx.x;   // float4 index
    if (i >= n * 32) return;
    int node = i >> 5;
    int head = (i & 31) >> 2;
    float z = g_Z[node * NHEADS + head];
    float s = 1.0f / (z + 1e-6f);
    float4 v = ((float4*)out)[i];
    v.x *= s; v.y *= s; v.z *= s; v.w *= s;
    ((float4*)out)[i] = v;
}

// ---------------------------------------------------------------------------
extern "C" void kernel_launch(void* const* d_in, const int* in_sizes, int n_in,
                              void* d_out, int out_size)
{
    const float* x  = (const float*)d_in[0];
    const int*   ei = (const int*)d_in[1];   // int32 (JAX default x64 disabled)
    // d_in[2] = virt_h, d_in[3] = virt_edge_index: unused dummies
    const float* Wq = (const float*)d_in[4];
    const float* bq = (const float*)d_in[5];
    const float* Wk = (const float*)d_in[6];
    const float* bk = (const float*)d_in[7];
    const float* Wv = (const float*)d_in[8];
    const float* bv = (const float*)d_in[9];
    float* out = (float*)d_out;

    int n = in_sizes[0] / 128;
    int E = in_sizes[1] / 2;

    const int smem_bytes = (64 * 128 + 128 * 128) * sizeof(float);  // 96 KB
    cudaFuncSetAttribute(qkv_gemm, cudaFuncAttributeMaxDynamicSharedMemorySize,
                         smem_bytes);

    dim3 gemm_grid((n + 63) / 64, 3);
    qkv_gemm<<<gemm_grid, 256, smem_bytes>>>(x, Wq, bq, Wk, bk, Wv, bv, n);

    int n_out_f4 = n * 32;        // n*128/4
    int n_z_f4   = n * 2;         // n*8/4
    zero_kernel<<<(n_out_f4 + 255) / 256, 256>>>(out, n_out_f4, n_z_f4);

    edge_kernel<<<(E * 32 + 255) / 256, 256>>>(ei, E, out);

    norm_kernel<<<(n_out_f4 + 255) / 256, 256>>>(out, n);
}